// round 5
// baseline (speedup 1.0000x reference)
#include <cuda_runtime.h>

// Problem-size upper bounds (match reference_code constants).
#define NMAX 100000
#define EMAX 500000
#define RMAX 512
#define CHUNK 1024
#define NBLK_MAX 128   // ceil(NMAX/CHUNK) = 98 <= 128

// Scratch (allocation-free rule -> __device__ globals, zero-initialized at load).
__device__ float  g_pb[NMAX];       // <x[n], w[96:160]>
__device__ float  g_pr[RMAX];       // <rel_emb[r], w[64:96]>
__device__ int    g_cnt[NMAX];      // degree histogram (left zeroed by k_agg)
__device__ int    g_off[NMAX + 1];  // CSR offsets (exclusive scan)
__device__ int    g_blk[NBLK_MAX];  // per-block partial sums
__device__ int    g_rank[EMAX];     // within-segment rank of each edge
__device__ float2 g_pack[EMAX];     // (exp(pr+pb), bits: j | r<<17) in CSR order

// NOTE: the pa[d] = <x[d], w[0:64]> term of the logit is constant within a
// softmax segment (segment key IS d), so it cancels in the normalized
// attention. We never compute it.

// Fused: per-node pb scalar + per-rel pr scalar + degree histogram.
// The histogram atomic's RETURN VALUE is the edge's within-segment rank.
// g_cnt is zero on entry (static zero-init first call; k_agg re-zeroes).
__global__ void k_pre_hist(const float* __restrict__ x, const float* __restrict__ re,
                           const float* __restrict__ w, const int* __restrict__ ei,
                           int n, int r, int e) {
    int gid  = blockIdx.x * blockDim.x + threadIdx.x;
    int warp = gid >> 5;
    int lane = gid & 31;
    // histogram + rank capture: first ceil(e/4) threads, 4 edges each
    int i4 = gid * 4;
    if (i4 + 3 < e) {
        int4 v = *(const int4*)(ei + i4);
        int4 rk;
        rk.x = atomicAdd(&g_cnt[v.x], 1);
        rk.y = atomicAdd(&g_cnt[v.y], 1);
        rk.z = atomicAdd(&g_cnt[v.z], 1);
        rk.w = atomicAdd(&g_cnt[v.w], 1);
        *(int4*)(g_rank + i4) = rk;
    } else if (i4 < e) {
        for (int i = i4; i < e; ++i) g_rank[i] = atomicAdd(&g_cnt[ei[i]], 1);
    }
    if (warp < n) {
        float x0 = x[warp * 64 + lane];
        float x1 = x[warp * 64 + 32 + lane];
        float pb = x0 * __ldg(&w[96 + lane]) + x1 * __ldg(&w[128 + lane]);
        #pragma unroll
        for (int o = 16; o; o >>= 1) pb += __shfl_xor_sync(0xffffffffu, pb, o);
        if (lane == 0) g_pb[warp] = pb;
    }
    if (warp < r) {
        float v = re[warp * 32 + lane] * __ldg(&w[64 + lane]);
        #pragma unroll
        for (int o = 16; o; o >>= 1) v += __shfl_xor_sync(0xffffffffu, v, o);
        if (lane == 0) g_pr[warp] = v;
    }
}

// Phase 1: per-block partial sums of g_cnt (CHUNK=1024 per 256-thread block).
__global__ void k_scan1(int n) {
    __shared__ int sw[8];
    int b = blockIdx.x, t = threadIdx.x;
    int base = b * CHUNK + t * 4;
    int s = 0;
    #pragma unroll
    for (int k = 0; k < 4; ++k) {
        int i = base + k;
        if (i < n) s += g_cnt[i];
    }
    #pragma unroll
    for (int o = 16; o; o >>= 1) s += __shfl_xor_sync(0xffffffffu, s, o);
    if ((t & 31) == 0) sw[t >> 5] = s;
    __syncthreads();
    if (t == 0) {
        int tot = 0;
        #pragma unroll
        for (int k = 0; k < 8; ++k) tot += sw[k];
        g_blk[b] = tot;
    }
}

// Phase 2: each block computes its own prefix over g_blk, then local scan.
__global__ void k_scan3(int n, int nblk, int e) {
    __shared__ int sh[256];
    __shared__ int swr[8];
    __shared__ int s_pref;
    int b = blockIdx.x, t = threadIdx.x;

    int pv = (t < b && t < nblk) ? g_blk[t] : 0;
    #pragma unroll
    for (int o = 16; o; o >>= 1) pv += __shfl_xor_sync(0xffffffffu, pv, o);
    if ((t & 31) == 0) swr[t >> 5] = pv;
    __syncthreads();
    if (t == 0) {
        int s = 0;
        #pragma unroll
        for (int k = 0; k < 8; ++k) s += swr[k];
        s_pref = s;
        if (b == 0) g_off[n] = e;
    }
    __syncthreads();

    int base = b * CHUNK + t * 4;
    int c[4];
    #pragma unroll
    for (int k = 0; k < 4; ++k) {
        int i = base + k;
        c[k] = (i < n) ? g_cnt[i] : 0;
    }
    int s = c[0] + c[1] + c[2] + c[3];
    sh[t] = s;
    __syncthreads();
    #pragma unroll
    for (int off = 1; off < 256; off <<= 1) {
        int u = (t >= off) ? sh[t - off] : 0;
        __syncthreads();
        sh[t] += u;
        __syncthreads();
    }
    int run = s_pref + sh[t] - s;   // exclusive thread offset
    #pragma unroll
    for (int k = 0; k < 4; ++k) {
        int i = base + k;
        if (i < n) g_off[i] = run;
        run += c[k];
    }
}

// Scatter edges into CSR order, atomic-free: pos = g_off[d] + rank.
// Stores exp(pr[r]+pb[j]) (pa cancels in the softmax). 2 edges per thread,
// loads batched before dependent math for MLP.
__global__ void __launch_bounds__(256) k_scatter(
        const int* __restrict__ ei, const int* __restrict__ ej,
        const int* __restrict__ rel, int e) {
    int i2 = (blockIdx.x * blockDim.x + threadIdx.x) * 2;
    if (i2 + 1 < e) {
        int2 d2 = *(const int2*)(ei + i2);
        int2 j2 = *(const int2*)(ej + i2);
        int2 r2 = *(const int2*)(rel + i2);
        int2 k2 = *(const int2*)(g_rank + i2);
        // issue all random loads up front
        int   o0 = g_off[d2.x];
        int   o1 = g_off[d2.y];
        float b0 = g_pb[j2.x];
        float b1 = g_pb[j2.y];
        float r0 = g_pr[r2.x];
        float r1 = g_pr[r2.y];
        float2 p0, p1;
        p0.x = __expf(r0 + b0);
        p0.y = __uint_as_float((unsigned)j2.x | ((unsigned)r2.x << 17));
        p1.x = __expf(r1 + b1);
        p1.y = __uint_as_float((unsigned)j2.y | ((unsigned)r2.y << 17));
        g_pack[o0 + k2.x] = p0;
        g_pack[o1 + k2.y] = p1;
    } else if (i2 < e) {
        for (int i = i2; i < e; ++i) {
            int d = ei[i], j = ej[i], r = rel[i];
            float2 p;
            p.x = __expf(g_pr[r] + g_pb[j]);
            p.y = __uint_as_float((unsigned)j | ((unsigned)r << 17));
            g_pack[g_off[d] + g_rank[i]] = p;
        }
    }
}

// One warp per node: weighted aggregate + output assembly. Also re-zeroes
// g_cnt for the next invocation.
__global__ void k_agg(const float* __restrict__ x, const float* __restrict__ re,
                      float* __restrict__ out, int n) {
    int warp = (blockIdx.x * blockDim.x + threadIdx.x) >> 5;
    int lane = threadIdx.x & 31;
    if (warp >= n) return;
    int beg = g_off[warp];
    int end = g_off[warp + 1];

    const float2* x2 = (const float2*)x;   // lane covers dims (2*lane, 2*lane+1)

    float s = 0.f, ar = 0.f;
    float2 aj = make_float2(0.f, 0.f);
    int k = beg;
    for (; k + 2 <= end; k += 2) {          // 2 independent edges per iter (MLP)
        float2 p0 = g_pack[k];
        float2 p1 = g_pack[k + 1];
        unsigned pk0 = __float_as_uint(p0.y);
        unsigned pk1 = __float_as_uint(p1.y);
        int j0 = (int)(pk0 & 0x1FFFFu), r0 = (int)(pk0 >> 17);
        int j1 = (int)(pk1 & 0x1FFFFu), r1 = (int)(pk1 >> 17);
        float  re0 = __ldg(&re[r0 * 32 + lane]);
        float  re1 = __ldg(&re[r1 * 32 + lane]);
        float2 xv0 = __ldg(&x2[j0 * 32 + lane]);
        float2 xv1 = __ldg(&x2[j1 * 32 + lane]);
        s    += p0.x + p1.x;
        ar   += p0.x * re0 + p1.x * re1;
        aj.x += p0.x * xv0.x + p1.x * xv1.x;
        aj.y += p0.x * xv0.y + p1.x * xv1.y;
    }
    if (k < end) {
        float2 p = g_pack[k];
        unsigned pk = __float_as_uint(p.y);
        int j = (int)(pk & 0x1FFFFu), r = (int)(pk >> 17);
        s    += p.x;
        ar   += p.x * __ldg(&re[r * 32 + lane]);
        float2 xv = __ldg(&x2[j * 32 + lane]);
        aj.x += p.x * xv.x;
        aj.y += p.x * xv.y;
    }
    float f  = 1.f / (s + 1e-16f);
    float sf = s * f;   // sum of normalized attention

    float2 xo = x2[warp * 32 + lane];
    float2* o2 = (float2*)(out + (long long)warp * 224);
    o2[lane]      = xo;                                                        // 0:64
    o2[32 + lane] = make_float2(fmaxf(0.f, xo.x * sf), fmaxf(0.f, xo.y * sf)); // 64:128
    out[(long long)warp * 224 + 128 + lane] = fmaxf(0.f, ar * f);              // 128:160
    o2[80 + lane] = make_float2(fmaxf(0.f, aj.x * f), fmaxf(0.f, aj.y * f));   // 160:224

    if (lane == 0) g_cnt[warp] = 0;        // reset for next call
}

extern "C" void kernel_launch(void* const* d_in, const int* in_sizes, int n_in,
                              void* d_out, int out_size) {
    const float* x    = (const float*)d_in[0];   // [N, 64]
    const int*   eidx = (const int*)  d_in[1];   // [2, E]
    const int*   rel  = (const int*)  d_in[2];   // [E]
    const float* re   = (const float*)d_in[3];   // [R, 32]
    const float* w    = (const float*)d_in[4];   // [160]

    int N = in_sizes[0] / 64;
    int E = in_sizes[2];
    int R = in_sizes[3] / 32;
    if (N > NMAX) N = NMAX;
    if (E > EMAX) E = EMAX;
    if (R > RMAX) R = RMAX;

    const int* ei = eidx;
    const int* ej = eidx + E;
    int nblk = (N + CHUNK - 1) / CHUNK;

    k_pre_hist<<<(N * 32 + 255) / 256, 256>>>(x, re, w, ei, N, R, E);
    k_scan1<<<nblk, 256>>>(N);
    k_scan3<<<nblk, 256>>>(N, nblk, E);
    k_scatter<<<(E / 2 + 256) / 256, 256>>>(ei, ej, rel, E);
    k_agg<<<(N * 32 + 255) / 256, 256>>>(x, re, (float*)d_out, N);
}

// round 6
// speedup vs baseline: 1.2248x; 1.2248x over previous
#include <cuda_runtime.h>

// Problem-size upper bounds (match reference_code constants).
#define NMAX 100000
#define EMAX 500000
#define RMAX 512

// Scratch (allocation-free rule -> __device__ globals, zero-initialized at load).
// g_head[d] == 0 means empty; otherwise edge index + 1. k_agg re-zeroes it
// after consuming, so every call sees the same initial state.
__device__ float g_pb[NMAX];     // <x[n], w[96:160]>
__device__ float g_pr[RMAX];     // <rel_emb[r], w[64:96]>
__device__ int   g_head[NMAX];   // per-destination list head (0 = empty)
__device__ int2  g_link[EMAX];   // (prev head, packed j | r<<17)

// NOTE: the pa[d] = <x[d], w[0:64]> logit term is constant within a softmax
// segment (segment key IS d), so it cancels in the normalized attention and
// is never computed. No segment-max shift needed either: |pr+pb| ~ O(1) for
// this weight scale, so exp is safe and ratios are mathematically identical
// (EPS=1e-16 perturbation is far below fp32 resolution).

// Fused: per-node pb scalar + per-rel pr scalar + linked-list build.
// List build: 1 coalesced int2 store + 1 atomicExch per edge. No scan needed.
__global__ void k_pre(const float* __restrict__ x, const float* __restrict__ re,
                      const float* __restrict__ w, const int* __restrict__ ei,
                      const int* __restrict__ ej, const int* __restrict__ rel,
                      int n, int r, int e) {
    int gid  = blockIdx.x * blockDim.x + threadIdx.x;
    int warp = gid >> 5;
    int lane = gid & 31;
    if (gid < e) {
        int d = ei[gid];
        int j = ej[gid];
        int rr = rel[gid];
        int old = atomicExch(&g_head[d], gid + 1);
        g_link[gid] = make_int2(old, (int)((unsigned)j | ((unsigned)rr << 17)));
    }
    if (warp < n) {
        float x0 = x[warp * 64 + lane];
        float x1 = x[warp * 64 + 32 + lane];
        float pb = x0 * __ldg(&w[96 + lane]) + x1 * __ldg(&w[128 + lane]);
        #pragma unroll
        for (int o = 16; o; o >>= 1) pb += __shfl_xor_sync(0xffffffffu, pb, o);
        if (lane == 0) g_pb[warp] = pb;
    }
    if (warp < r) {
        float v = re[warp * 32 + lane] * __ldg(&w[64 + lane]);
        #pragma unroll
        for (int o = 16; o; o >>= 1) v += __shfl_xor_sync(0xffffffffu, v, o);
        if (lane == 0) g_pr[warp] = v;
    }
}

// One warp per node: walk the edge list, softmax-weighted aggregate, write
// output (streaming stores so the 90MB output doesn't evict x/link from L2),
// reset list head for the next invocation.
__global__ void k_agg(const float* __restrict__ x, const float* __restrict__ re,
                      float* __restrict__ out, int n) {
    int warp = (blockIdx.x * blockDim.x + threadIdx.x) >> 5;
    int lane = threadIdx.x & 31;
    if (warp >= n) return;

    const float2* x2 = (const float2*)x;   // lane covers dims (2*lane, 2*lane+1)

    int cur = g_head[warp];
    float s = 0.f, ar = 0.f;
    float2 aj = make_float2(0.f, 0.f);
    while (cur) {
        int2 ln = g_link[cur - 1];          // 8B broadcast load (warp-uniform)
        cur = ln.x;                          // chase next immediately
        unsigned pk = (unsigned)ln.y;
        int j  = (int)(pk & 0x1FFFFu);
        int rr = (int)(pk >> 17);
        float wgt = __expf(__ldg(&g_pr[rr]) + __ldg(&g_pb[j]));
        s  += wgt;
        ar += wgt * __ldg(&re[rr * 32 + lane]);
        float2 xv = __ldg(&x2[j * 32 + lane]);
        aj.x += wgt * xv.x;
        aj.y += wgt * xv.y;
    }
    float f  = 1.f / (s + 1e-16f);
    float sf = s * f;   // sum of normalized attention

    float2 xo = x2[warp * 32 + lane];
    float2* o2 = (float2*)(out + (long long)warp * 224);
    __stcs(&o2[lane], xo);                                                      // 0:64
    __stcs(&o2[32 + lane],
           make_float2(fmaxf(0.f, xo.x * sf), fmaxf(0.f, xo.y * sf)));          // 64:128
    __stcs(out + (long long)warp * 224 + 128 + lane, fmaxf(0.f, ar * f));       // 128:160
    __stcs(&o2[80 + lane],
           make_float2(fmaxf(0.f, aj.x * f), fmaxf(0.f, aj.y * f)));            // 160:224

    if (lane == 0) g_head[warp] = 0;        // reset for next call
}

extern "C" void kernel_launch(void* const* d_in, const int* in_sizes, int n_in,
                              void* d_out, int out_size) {
    const float* x    = (const float*)d_in[0];   // [N, 64]
    const int*   eidx = (const int*)  d_in[1];   // [2, E]
    const int*   rel  = (const int*)  d_in[2];   // [E]
    const float* re   = (const float*)d_in[3];   // [R, 32]
    const float* w    = (const float*)d_in[4];   // [160]

    int N = in_sizes[0] / 64;
    int E = in_sizes[2];
    int R = in_sizes[3] / 32;
    if (N > NMAX) N = NMAX;
    if (E > EMAX) E = EMAX;
    if (R > RMAX) R = RMAX;

    const int* ei = eidx;
    const int* ej = eidx + E;

    long long pre_threads = (long long)N * 32;
    if (pre_threads < E) pre_threads = E;

    k_pre<<<(int)((pre_threads + 255) / 256), 256>>>(x, re, w, ei, ej, rel, N, R, E);
    k_agg<<<(N * 32 + 255) / 256, 256>>>(x, re, (float*)d_out, N);
}